// round 7
// baseline (speedup 1.0000x reference)
#include <cuda_runtime.h>
#include <cuda_bf16.h>
#include <cstdint>

// ---------------------------------------------------------------------------
// GCNArchEmbedder via mma.sync bf16 (HMMA), 3-pass hi/lo fp32 emulation.
// R7: fused U01 operand table (halves phase-1 table loads);
//     B fragments read via __ldg from L1D (no smem copy); 2 CTAs/SM.
// ---------------------------------------------------------------------------

#define NUM_PRIM   8
#define OPD        48
#define OPH        48
#define GD         128
#define ROWS       65536
#define TILE_M     64
#define U01S       130      // fused-table k-stride (banks: pair*2+k mod 32)

// table rows: 0..7 U0''[p] (=U0+Uc), 8..15 U1[p], 16..17 H1init
__device__ float g_tab[18 * GD];
// W2 fragments: idx = (ks*16 + ntile)*32 + lane ; {b0hi, b1hi, b0lo, b1lo}
__device__ uint4 g_bfrag[4096];

typedef unsigned long long ull;
__device__ __forceinline__ ull pk2(float lo, float hi) {
    ull r; asm("mov.b64 %0, {%1, %2};" : "=l"(r) : "f"(lo), "f"(hi)); return r;
}
__device__ __forceinline__ void unpk2(float& lo, float& hi, ull v) {
    asm("mov.b64 {%0, %1}, %2;" : "=f"(lo), "=f"(hi) : "l"(v));
}
__device__ __forceinline__ ull mul2(ull a, ull b) {
    ull r; asm("mul.rn.f32x2 %0, %1, %2;" : "=l"(r) : "l"(a), "l"(b)); return r;
}
__device__ __forceinline__ void fma2(ull& d, ull a, ull b) {
    asm("fma.rn.f32x2 %0, %1, %2, %0;" : "+l"(d) : "l"(a), "l"(b));
}
// low half = first arg (k-even element)
__device__ __forceinline__ uint32_t bf16x2(float lo, float hi) {
    uint32_t r; asm("cvt.rn.bf16x2.f32 %0, %1, %2;" : "=r"(r) : "f"(hi), "f"(lo)); return r;
}
__device__ __forceinline__ float bf_lo(uint32_t u) { return __uint_as_float(u << 16); }
__device__ __forceinline__ float bf_hi(uint32_t u) { return __uint_as_float(u & 0xffff0000u); }

__device__ __forceinline__ void mma_bf16(float* d, const uint32_t* a,
                                         uint32_t b0, uint32_t b1) {
    asm volatile(
        "mma.sync.aligned.m16n8k16.row.col.f32.bf16.bf16.f32 "
        "{%0,%1,%2,%3}, {%4,%5,%6,%7}, {%8,%9}, {%0,%1,%2,%3};"
        : "+f"(d[0]), "+f"(d[1]), "+f"(d[2]), "+f"(d[3])
        : "r"(a[0]), "r"(a[1]), "r"(a[2]), "r"(a[3]), "r"(b0), "r"(b1));
}

// ---------------------------------------------------------------------------
// Prep kernel, <<<25, 256>>>:
//   blocks 0..7 : U0''[p] (full Uc folded), U1[p]   block 8 : H1init rows
//   blocks 9..24: W2 fragment pack
// ---------------------------------------------------------------------------
__global__ void gcn_prep_kernel(const float* __restrict__ init_emb,
                                const float* __restrict__ op_emb,
                                const float* __restrict__ xw,
                                const float* __restrict__ xb,
                                const float* __restrict__ w1,
                                const float* __restrict__ w2) {
    const int b = blockIdx.x;
    const int t = threadIdx.x;

    if (b < 8) {                       // primitive p = b
        __shared__ float T[2][OPH];
        if (t < 96) {
            const int which = t / 48, h = t % 48;
            float s0 = 0.f, s1 = 0.f;
            const int db = which * OPD;
            for (int d = 0; d < OPD; d += 2) {
                s0 = fmaf(op_emb[b * OPD + d],     xw[(db + d) * OPH + h],     s0);
                s1 = fmaf(op_emb[b * OPD + d + 1], xw[(db + d + 1) * OPH + h], s1);
            }
            T[which][h] = s0 + s1;
        }
        __syncthreads();
        const int which = t >> 7, f = t & 127;
        float s0 = 0.f, s1 = 0.f, uc = 0.f;
        for (int h = 0; h < OPH; h += 2) {
            float wa = w1[h * GD + f], wb = w1[(h + 1) * GD + f];
            s0 = fmaf(T[which][h],     wa, s0);
            s1 = fmaf(T[which][h + 1], wb, s1);
            uc = fmaf(xb[h], wa, fmaf(xb[h + 1], wb, uc));
        }
        g_tab[(which * 8 + b) * GD + f] = s0 + s1 + (which == 0 ? uc : 0.f);
    } else if (b == 8) {               // init rows
        __shared__ float Y[2][OPH];
        if (t < 96) {
            const int kk = t / 48, h = t % 48;
            float s0 = xb[h], s1 = 0.f;
            for (int d = 0; d < 2 * OPD; d += 2) {
                s0 = fmaf(init_emb[kk * 2 * OPD + d],     xw[d * OPH + h],       s0);
                s1 = fmaf(init_emb[kk * 2 * OPD + d + 1], xw[(d + 1) * OPH + h], s1);
            }
            Y[kk][h] = s0 + s1;
        }
        __syncthreads();
        const int kk = t >> 7, f = t & 127;
        float s0 = 0.f, s1 = 0.f;
        for (int h = 0; h < OPH; h += 2) {
            s0 = fmaf(Y[kk][h],     w1[h * GD + f],       s0);
            s1 = fmaf(Y[kk][h + 1], w1[(h + 1) * GD + f], s1);
        }
        g_tab[(16 + kk) * GD + f] = s0 + s1;
    } else {                           // W2 pack
        const int idx = (b - 9) * 256 + t;   // 0..4095
        const int lane = idx & 31;
        const int nt   = (idx >> 5) & 15;
        const int ks   = idx >> 9;
        const int k0 = ks * 16 + (lane & 3) * 2;
        const int n  = nt * 8 + (lane >> 2);
        float w00 = w2[k0 * GD + n];
        float w01 = w2[(k0 + 1) * GD + n];
        float w10 = w2[(k0 + 8) * GD + n];
        float w11 = w2[(k0 + 9) * GD + n];
        uint32_t b0h = bf16x2(w00, w01);
        uint32_t b1h = bf16x2(w10, w11);
        uint32_t b0l = bf16x2(w00 - bf_lo(b0h), w01 - bf_hi(b0h));
        uint32_t b1l = bf16x2(w10 - bf_lo(b1h), w11 - bf_hi(b1h));
        g_bfrag[idx] = make_uint4(b0h, b1h, b0l, b1l);
    }
}

// ---------------------------------------------------------------------------
// Main kernel (TILE_M = 64, 512 threads, 2 CTAs/SM). smem byte layout:
//   AH   0      (16384)  [g4][ks8][pos32] uint4, XOR-swizzled pos
//   AL   16384  (16384)
//   U01  32768  (33280)  64 x U01S floats, fused U0''[o0]+U1[o1]
//   P01  66048  (1024)   H1init rows (2 x 128)
//   arch 67072  (4096)
// total 71168 B  -> 2 CTAs/SM; B frags stay in gmem, served by L1D.
// ---------------------------------------------------------------------------
#define SM_AH    0
#define SM_AL    16384
#define SM_U01   32768
#define SM_P01   66048
#define SM_ARCH  67072
#define SMEM_BYTES 71168

__global__ void __launch_bounds__(512, 2)
gcn_main_kernel(const int* __restrict__ archs, float* __restrict__ out) {
    extern __shared__ char smem[];
    float* u01   = (float*)(smem + SM_U01);
    float* p01   = (float*)(smem + SM_P01);
    int*  archsm = (int*)(smem + SM_ARCH);

    const int tid  = threadIdx.x;
    const int wid  = tid >> 5;
    const int lane = tid & 31;
    const int rowbase = blockIdx.x * TILE_M;

    // ---- build fused U01 table + stage init rows + archs ----
    {
        for (int idx = tid; idx < 4096; idx += 512) {      // float2 granularity
            const int pair = idx >> 6;                     // 0..63
            const int k2 = idx & 63;
            const int o0 = pair >> 3, o1 = pair & 7;
            float2 a = *(const float2*)(g_tab + o0 * GD + k2 * 2);
            float2 b = *(const float2*)(g_tab + (8 + o1) * GD + k2 * 2);
            *(float2*)(u01 + pair * U01S + k2 * 2) = make_float2(a.x + b.x, a.y + b.y);
        }
        if (tid < 128) {
            float2 v = *(const float2*)(g_tab + 16 * GD + tid * 2);
            *(float2*)(p01 + tid * 2) = v;
        }
        if (tid < 256) {
            const int4* av = (const int4*)archs + (size_t)rowbase * 4;
            ((int4*)archsm)[tid] = av[tid];
        }
    }
    __syncthreads();

    // =======================================================================
    // Phase 1: thread (row, ks) builds bf16 hi/lo A-fragments in smem.
    // Node embeddings h2..h5 are single fused-table loads.
    // =======================================================================
    {
        const int row = tid & 63;
        const int ks  = tid >> 6;          // 0..7
        const int g_  = row >> 4;
        const int r   = row & 7;
        const bool hiRole = ((row & 8) == 0);

        const int* ar = archsm + row * 16;
        int pe[8], oe[8];
#pragma unroll
        for (int e = 0; e < 8; e++) { pe[e] = ar[e]; oe[e] = ar[8 + e]; }

        float Af[4][6];
        float mmv[4];
#pragma unroll
        for (int s = 0; s < 4; s++) {
#pragma unroll
            for (int j = 0; j < 6; j++)
                Af[s][j] = (pe[2 * s] == j ? 1.f : 0.f) + (pe[2 * s + 1] == j ? 1.f : 0.f);
            float c = 0.f;
#pragma unroll
            for (int e = 0; e < 8; e++) c += (pe[e] == s + 2) ? 1.f : 0.f;
            mmv[s] = c * 0.25f;
        }

        const float* q0 = u01 + (oe[0] * 8 + oe[1]) * U01S;
        const float* q1 = u01 + (oe[2] * 8 + oe[3]) * U01S;
        const float* q2 = u01 + (oe[4] * 8 + oe[5]) * U01S;
        const float* q3 = u01 + (oe[6] * 8 + oe[7]) * U01S;
        const float* p0 = p01;
        const float* p1 = p01 + GD;

        auto paircomp = [&](int k, uint32_t& hi2, uint32_t& lo2) {
            ull h0 = *(const ull*)(p0 + k);
            ull h1 = *(const ull*)(p1 + k);
            ull h2 = *(const ull*)(q0 + k);
            ull h3 = *(const ull*)(q1 + k);
            ull h4 = *(const ull*)(q2 + k);
            ull h5 = *(const ull*)(q3 + k);
            float a0 = 0.f, a1 = 0.f;
#pragma unroll
            for (int s = 0; s < 4; s++) {
                ull z = mul2(pk2(Af[s][0], Af[s][0]), h0);
                fma2(z, pk2(Af[s][1], Af[s][1]), h1);
                fma2(z, pk2(Af[s][2], Af[s][2]), h2);
                fma2(z, pk2(Af[s][3], Af[s][3]), h3);
                fma2(z, pk2(Af[s][4], Af[s][4]), h4);
                fma2(z, pk2(Af[s][5], Af[s][5]), h5);
                float zl, zh; unpk2(zl, zh, z);
                zl = fmaxf(zl, 0.f);
                zh = fmaxf(zh, 0.f);
                a0 = fmaf(mmv[s], zl, a0);
                a1 = fmaf(mmv[s], zh, a1);
            }
            hi2 = bf16x2(a0, a1);
            lo2 = bf16x2(a0 - bf_lo(hi2), a1 - bf_hi(hi2));
        };

        char* slotH = smem + SM_AH + (g_ * 8 + ks) * 512;
        char* slotL = smem + SM_AL + (g_ * 8 + ks) * 512;
#pragma unroll
        for (int j = 0; j < 4; j++) {
            uint32_t hA, lA, hC, lC;
            paircomp(ks * 16 + 2 * j, hA, lA);
            paircomp(ks * 16 + 2 * j + 8, hC, lC);
            uint32_t ohA = __shfl_xor_sync(0xffffffffu, hA, 8);
            uint32_t ohC = __shfl_xor_sync(0xffffffffu, hC, 8);
            uint32_t olA = __shfl_xor_sync(0xffffffffu, lA, 8);
            uint32_t olC = __shfl_xor_sync(0xffffffffu, lC, 8);
            const int pos = r * 4 + (j ^ ((r >> 1) & 3));
            if (hiRole) {
                *(uint4*)(slotH + pos * 16) = make_uint4(hA, ohA, hC, ohC);
            } else {
                *(uint4*)(slotL + pos * 16) = make_uint4(olA, lA, olC, lC);
            }
        }
    }
    __syncthreads();

    // =======================================================================
    // Phase 2: warp (rg, cg) = rows [16rg,+16) x cols [32cg,+32); 3-pass mma.
    // B fragments via __ldg (L1D-resident, read-only).
    // =======================================================================
    {
        const int rg = wid >> 2;
        const int cg = wid & 3;
        const int pos = (lane & 28) | ((lane ^ (lane >> 3)) & 3);

        float acc[4][4];
#pragma unroll
        for (int nt = 0; nt < 4; nt++)
#pragma unroll
            for (int j = 0; j < 4; j++) acc[nt][j] = 0.f;

#pragma unroll
        for (int ks = 0; ks < 8; ks++) {
            const uint4* AHp = (const uint4*)(smem + SM_AH + (rg * 8 + ks) * 512);
            const uint4* ALp = (const uint4*)(smem + SM_AL + (rg * 8 + ks) * 512);
            uint4 ah = AHp[pos];
            uint4 al = ALp[pos];
            const uint4* Bp = g_bfrag + (ks * 16 + cg * 4) * 32 + lane;
#pragma unroll
            for (int nt = 0; nt < 4; nt++) {
                uint4 B = __ldg(Bp + nt * 32);
                mma_bf16(acc[nt], (const uint32_t*)&ah, B.x, B.y);
                mma_bf16(acc[nt], (const uint32_t*)&ah, B.z, B.w);
                mma_bf16(acc[nt], (const uint32_t*)&al, B.x, B.y);
            }
        }

        // ---- epilogue ----
        float* ob = out + (size_t)rowbase * GD;
        const int r0 = rg * 16 + (lane >> 2);
#pragma unroll
        for (int nt = 0; nt < 4; nt++) {
            const int c = cg * 32 + nt * 8 + (lane & 3) * 2;
            *(float2*)(ob + (size_t)r0 * GD + c) = make_float2(acc[nt][0], acc[nt][1]);
            *(float2*)(ob + (size_t)(r0 + 8) * GD + c) = make_float2(acc[nt][2], acc[nt][3]);
        }
    }
}

// ---------------------------------------------------------------------------
extern "C" void kernel_launch(void* const* d_in, const int* in_sizes, int n_in,
                              void* d_out, int out_size) {
    const int*   archs    = (const int*)  d_in[0];
    const float* init_emb = (const float*)d_in[1];
    const float* op_emb   = (const float*)d_in[2];
    const float* xw       = (const float*)d_in[3];
    const float* xb       = (const float*)d_in[4];
    const float* w1       = (const float*)d_in[5];
    const float* w2       = (const float*)d_in[6];
    float* out = (float*)d_out;

    cudaFuncSetAttribute(gcn_main_kernel,
                         cudaFuncAttributeMaxDynamicSharedMemorySize, SMEM_BYTES);

    gcn_prep_kernel<<<25, 256>>>(init_emb, op_emb, xw, xb, w1, w2);
    gcn_main_kernel<<<ROWS / TILE_M, 512, SMEM_BYTES>>>(archs, out);
}